// round 10
// baseline (speedup 1.0000x reference)
#include <cuda_runtime.h>

#define MAXN 4096
#define IMG_W 128
#define IMG_H 128
#define TILE 8
#define TILES_X 16
#define TILES_Y 16
#define GRID2 256
#define BLK2 256
#define FXc 300.0f
#define FYc 300.0f
#define LOG2E 1.4426950408889634f

// ---- scratch (allocation-free per harness rules) ----
__device__ float4 g_cull[MAXN];   // (u, v, r2, z)      [geom]
__device__ float4 g_a[MAXN];      // (u, v, A2, B2)     [geom]
__device__ float2 g_q[MAXN];      // (Cc2, op_eff)      [geom]
__device__ float4 g_col[MAXN];    // (r, g, b, -)       [color, per-channel writers]
__device__ unsigned int g_leaf[8];   // monotonic two-level barrier
__device__ unsigned int g_root;

__device__ __constant__ float C0 = 0.28209479177387814f;
__device__ __constant__ float C1 = 0.4886025119029199f;
__device__ __constant__ float C2_[5] = {1.0925484305920792f, -1.0925484305920792f,
                                        0.31539156525252005f, -1.0925484305920792f,
                                        0.5462742152960396f};
__device__ __constant__ float C3_[7] = {-0.5900435899266435f, 2.890611442640554f,
                                        -0.4570457994644658f, 0.3731763325901154f,
                                        -0.4570457994644658f, 1.445305721320277f,
                                        -0.5900435899266435f};

// Two-level monotonic barrier (replay-safe: counters only grow, +GRID2 per launch).
// 256 blocks: leaf blk&7 → 32 same-address arrivals spread over 8 L2 slots;
// 32nd arrival of a leaf round bumps root; waiters poll root only.
__device__ __forceinline__ void gbar() {
    __syncthreads();
    __threadfence();
    if (threadIdx.x == 0) {
        int leaf = blockIdx.x & 7;
        unsigned int old = atomicAdd(&g_leaf[leaf], 1u);
        if ((old & 31u) == 31u) atomicAdd(&g_root, 1u);
        unsigned int target = ((old >> 5) + 1u) * 8u;
        while (*((volatile unsigned int*)&g_root) < target) { __nanosleep(32); }
        __threadfence();
    }
    __syncthreads();
}

__global__ void __launch_bounds__(BLK2, 2) fused_kernel(
        const float* __restrict__ pw,
        const float* __restrict__ lowsh,
        const float* __restrict__ highsh,
        const float* __restrict__ rawop,
        const float* __restrict__ sraw,
        const float* __restrict__ rraw,
        const float* __restrict__ Rcw,
        const float* __restrict__ tcw,
        float* __restrict__ out,
        int n) {
    int t   = threadIdx.x;
    int blk = blockIdx.x;
    int gid = blk * BLK2 + t;

    // ---------------- Phase A: geom || color on disjoint threads ----------------
    if (gid < n) {
        // ---- geom: projection, covariance, cull radius ----
        int i = gid;

        float R00=Rcw[0],R01=Rcw[1],R02=Rcw[2];
        float R10=Rcw[3],R11=Rcw[4],R12=Rcw[5];
        float R20=Rcw[6],R21=Rcw[7],R22=Rcw[8];
        float t0=tcw[0], t1=tcw[1], t2=tcw[2];

        float px = pw[i*3+0], py = pw[i*3+1], pz = pw[i*3+2];

        float pc0 = R00*px + R01*py + R02*pz + t0;
        float pc1 = R10*px + R11*py + R12*pz + t1;
        float pc2 = R20*px + R21*py + R22*pz + t2;
        float invz = 1.0f / pc2;
        float u = FXc * pc0 * invz + 0.5f * IMG_W;
        float v = FYc * pc1 * invz + 0.5f * IMG_H;

        float op = 1.0f / (1.0f + __expf(-rawop[i]));

        float s0 = __expf(sraw[i*3+0]);
        float s1 = __expf(sraw[i*3+1]);
        float s2 = __expf(sraw[i*3+2]);

        float qw = rraw[i*4+0], qx = rraw[i*4+1], qy = rraw[i*4+2], qz = rraw[i*4+3];
        float qn = rsqrtf(qw*qw + qx*qx + qy*qy + qz*qz);
        qw *= qn; qx *= qn; qy *= qn; qz *= qn;

        float Rg00 = 1.0f - 2.0f*(qy*qy + qz*qz);
        float Rg01 = 2.0f*(qx*qy - qw*qz);
        float Rg02 = 2.0f*(qx*qz + qw*qy);
        float Rg10 = 2.0f*(qx*qy + qw*qz);
        float Rg11 = 1.0f - 2.0f*(qx*qx + qz*qz);
        float Rg12 = 2.0f*(qy*qz - qw*qx);
        float Rg20 = 2.0f*(qx*qz - qw*qy);
        float Rg21 = 2.0f*(qy*qz + qw*qx);
        float Rg22 = 1.0f - 2.0f*(qx*qx + qy*qy);

        float M00 = Rg00*s0, M01 = Rg01*s1, M02 = Rg02*s2;
        float M10 = Rg10*s0, M11 = Rg11*s1, M12 = Rg12*s2;
        float M20 = Rg20*s0, M21 = Rg21*s1, M22 = Rg22*s2;

        float j00 = FXc*invz, j02 = -FXc*pc0*invz*invz;
        float j11 = FYc*invz, j12 = -FYc*pc1*invz*invz;
        float T00 = j00*R00 + j02*R20;
        float T01 = j00*R01 + j02*R21;
        float T02 = j00*R02 + j02*R22;
        float T10 = j11*R10 + j12*R20;
        float T11 = j11*R11 + j12*R21;
        float T12 = j11*R12 + j12*R22;

        float V00 = T00*M00 + T01*M10 + T02*M20;
        float V01 = T00*M01 + T01*M11 + T02*M21;
        float V02 = T00*M02 + T01*M12 + T02*M22;
        float V10 = T10*M00 + T11*M10 + T12*M20;
        float V11 = T10*M01 + T11*M11 + T12*M21;
        float V12 = T10*M02 + T11*M12 + T12*M22;

        float a  = V00*V00 + V01*V01 + V02*V02 + 0.3f;
        float b  = V00*V10 + V01*V11 + V02*V12;
        float cc = V10*V10 + V11*V11 + V12*V12 + 0.3f;
        float det = a*cc - b*b;
        float idet = 1.0f / det;
        float ia =  cc * idet;
        float ib = -b  * idet;
        float ic =  a  * idet;

        float op_eff = (pc2 > 0.2f) ? op : 0.0f;

        float A2  = -0.5f * ia * LOG2E;
        float B2  = -ib * LOG2E;
        float Cc2 = -0.5f * ic * LOG2E;

        float mid  = 0.5f * (a + cc);
        float disc = sqrtf(0.25f * (a - cc) * (a - cc) + b * b);
        float lmax = mid + disc;
        float t255 = 255.0f * op_eff;
        float r2 = (t255 > 1.0f) ? 2.0f * __logf(t255) * lmax * 1.0002f : -1.0f;

        g_cull[i] = make_float4(u, v, r2, pc2);
        g_a[i]    = make_float4(u, v, A2, B2);
        g_q[i]    = make_float2(Cc2, op_eff);
    } else if (gid < 4 * n) {
        // ---- color: SH -> rgb, 3 threads per gaussian (one channel each) ----
        int cid = gid - n;
        int i  = cid / 3;
        int ch = cid - 3 * i;

        float R00=Rcw[0],R01=Rcw[1],R02=Rcw[2];
        float R10=Rcw[3],R11=Rcw[4],R12=Rcw[5];
        float R20=Rcw[6],R21=Rcw[7],R22=Rcw[8];
        float t0=tcw[0], t1=tcw[1], t2=tcw[2];

        float px = pw[i*3+0], py = pw[i*3+1], pz = pw[i*3+2];

        float dx0 = px + (R00*t0 + R10*t1 + R20*t2);
        float dy0 = py + (R01*t0 + R11*t1 + R21*t2);
        float dz0 = pz + (R02*t0 + R12*t1 + R22*t2);
        float dn = rsqrtf(dx0*dx0 + dy0*dy0 + dz0*dz0);
        float x = dx0*dn, y = dy0*dn, z = dz0*dn;

        float xx = x*x, yy = y*y, zz = z*z;
        float xy = x*y, yz = y*z, xz = x*z;

        const float* hs = highsh + i*45 + ch;
        float res = C0 * lowsh[i*3+ch];
        res += (-C1*y) * hs[0*3] + (C1*z) * hs[1*3] + (-C1*x) * hs[2*3];
        res += (C2_[0]*xy) * hs[3*3] + (C2_[1]*yz) * hs[4*3]
             + (C2_[2]*(2.0f*zz - xx - yy)) * hs[5*3]
             + (C2_[3]*xz) * hs[6*3] + (C2_[4]*(xx - yy)) * hs[7*3];
        res += (C3_[0]*y*(3.0f*xx - yy)) * hs[8*3]
             + (C3_[1]*xy*z) * hs[9*3]
             + (C3_[2]*y*(4.0f*zz - xx - yy)) * hs[10*3]
             + (C3_[3]*z*(2.0f*zz - 3.0f*xx - 3.0f*yy)) * hs[11*3]
             + (C3_[4]*x*(4.0f*zz - xx - yy)) * hs[12*3]
             + (C3_[5]*z*(xx - yy)) * hs[13*3]
             + (C3_[6]*x*(xx - 3.0f*yy)) * hs[14*3];
        ((float*)&g_col[i])[ch] = fmaxf(res + 0.5f, 0.0f);
    }

    gbar();

    // ------- Phase C: cull -> in-block stable sort -> split-K blend -> compose ----
    {
        __shared__ unsigned short slist[MAXN];     // culled original indices (any order)
        __shared__ float          szl[MAXN];       // their z
        __shared__ unsigned short sorted[MAXN];    // depth-sorted indices
        __shared__ int scnt;
        __shared__ float4 ca[4][64], cb[4][64];
        __shared__ float  ccb[4][64];
        __shared__ float4 part[4][64];

        int tlx = blk & (TILES_X - 1);
        int tly = blk >> 4;

        float xlo = tlx * TILE + 0.5f, xhi = tlx * TILE + (TILE - 0.5f);
        float ylo = tly * TILE + 0.5f, yhi = tly * TILE + (TILE - 0.5f);

        int lid = t & 31;
        unsigned lmask = (1u << lid) - 1u;

        if (t == 0) scnt = 0;
        __syncthreads();

        // cull: sync-free compaction (order fixed by the sort below)
        for (int c = 0; c < n; c += BLK2) {
            int i = c + t;
            int pred = 0;
            float zval = 0.0f;
            if (i < n) {
                float4 C4 = g_cull[i];
                float cu = fminf(fmaxf(C4.x, xlo), xhi);
                float cv = fminf(fmaxf(C4.y, ylo), yhi);
                float ddx = C4.x - cu, ddy = C4.y - cv;
                pred = (ddx * ddx + ddy * ddy <= C4.z) ? 1 : 0;
                zval = C4.w;
            }
            unsigned m = __ballot_sync(0xffffffffu, pred);
            int wbase = 0;
            if (lid == 0 && m) wbase = atomicAdd(&scnt, __popc(m));
            wbase = __shfl_sync(0xffffffffu, wbase, 0);
            if (pred) {
                int off = wbase + __popc(m & lmask);
                slist[off] = (unsigned short)i;
                szl[off]   = zval;
            }
        }
        __syncthreads();
        int cnt = scnt;

        // stable rank-sort by (z, original index) — deterministic regardless of
        // compaction order
        for (int j = t; j < cnt; j += BLK2) {
            float zj = szl[j];
            int   ij = slist[j];
            int rank = 0;
            for (int k = 0; k < cnt; k++) {
                float zk = szl[k];
                rank += (zk < zj) || (zk == zj && slist[k] < ij);
            }
            sorted[rank] = (unsigned short)ij;
        }
        __syncthreads();

        // split-K blend: quarter q of threads blends list-quarter q for all 64 px
        int q = t >> 6;
        int p = t & 63;
        float pxf = tlx * TILE + (p & 7) + 0.5f;
        float pyf = tly * TILE + (p >> 3) + 0.5f;

        int L4 = (cnt + 3) >> 2;
        int qbeg = q * L4;
        int qend = min(cnt, qbeg + L4);

        float T = 1.0f, cr = 0.0f, cg = 0.0f, cbl = 0.0f;

        for (int base = 0; base < L4; base += 64) {
            int src = qbeg + base + p;
            if (src < qend) {
                int idx = sorted[src];
                float2 Q  = g_q[idx];
                float4 CL = g_col[idx];
                ca[q][p]  = g_a[idx];
                cb[q][p]  = make_float4(Q.x, Q.y, CL.x, CL.y);
                ccb[q][p] = CL.z;
            }
            __syncthreads();
            int m = min(64, qend - (qbeg + base));
            #pragma unroll 4
            for (int k = 0; k < m; k++) {
                float4 A = ca[q][k];
                float4 B = cb[q][k];
                float dx = A.x - pxf;
                float dy = A.y - pyf;
                float pp = A.z * dx * dx;
                pp = fmaf(B.x, dy * dy, pp);
                pp = fmaf(A.w, dx * dy, pp);
                pp = fminf(pp, 0.0f);
                float gw;
                asm("ex2.approx.f32 %0, %1;" : "=f"(gw) : "f"(pp));
                float alpha = fminf(0.99f, B.y * gw);
                alpha = (alpha >= (1.0f / 255.0f)) ? alpha : 0.0f;
                float w = T * alpha;
                cr  = fmaf(w, B.z, cr);
                cg  = fmaf(w, B.w, cg);
                cbl = fmaf(w, ccb[q][k], cbl);
                T = fmaf(-alpha, T, T);
            }
            __syncthreads();
        }

        part[q][p] = make_float4(cr, cg, cbl, T);
        __syncthreads();

        // compose 4 quarters front-to-back (threads 0..63)
        if (t < 64) {
            float Tc = 1.0f, rr = 0.0f, gg = 0.0f, bb = 0.0f;
            #pragma unroll
            for (int s = 0; s < 4; s++) {
                float4 P = part[s][t];
                rr = fmaf(Tc, P.x, rr);
                gg = fmaf(Tc, P.y, gg);
                bb = fmaf(Tc, P.z, bb);
                Tc *= P.w;
            }
            int pxi = tlx * TILE + (t & 7);
            int pyi = tly * TILE + (t >> 3);
            int o = (pyi * IMG_W + pxi) * 3;
            out[o + 0] = rr;
            out[o + 1] = gg;
            out[o + 2] = bb;
        }
    }
}

extern "C" void kernel_launch(void* const* d_in, const int* in_sizes, int n_in,
                              void* d_out, int out_size) {
    const float* pw     = (const float*)d_in[0];
    const float* lowsh  = (const float*)d_in[1];
    const float* highsh = (const float*)d_in[2];
    const float* rawop  = (const float*)d_in[3];
    const float* sraw   = (const float*)d_in[4];
    const float* rraw   = (const float*)d_in[5];
    const float* Rcw    = (const float*)d_in[6];
    const float* tcw    = (const float*)d_in[7];
    int n = in_sizes[0] / 3;

    fused_kernel<<<GRID2, BLK2>>>(pw, lowsh, highsh, rawop, sraw, rraw, Rcw, tcw,
                                  (float*)d_out, n);
}

// round 11
// speedup vs baseline: 1.2049x; 1.2049x over previous
#include <cuda_runtime.h>

#define MAXN 4096
#define IMG_W 128
#define IMG_H 128
#define TILE_W 8
#define TILE_H 4
#define TILES_X 16
#define TILES_Y 32
#define NTILES 512
#define GRID3 512
#define BLK3 256
#define FXc 300.0f
#define FYc 300.0f
#define LOG2E 1.4426950408889634f

// ---- scratch (allocation-free per harness rules) ----
__device__ int    g_rank[MAXN];   // zeroed at end of each launch (and statically)
__device__ float4 g_a[MAXN];      // (u, v, A2, B2)     [geom]
__device__ float4 g_d[MAXN];      // (Cc2, op_eff, r2, -) [geom]
__device__ float4 g_col[MAXN];    // (r, g, b, -)       [color, per-channel writers]
__device__ float4 s_a[MAXN];      // sorted (u, v, A2, B2)
__device__ float4 s_b[MAXN];      // sorted (Cc2, op, colR, colG)
__device__ float2 s_c[MAXN];      // sorted (colB, r2)
__device__ unsigned int g_leaf[16];  // monotonic two-level barrier
__device__ unsigned int g_root;

__device__ __constant__ float C0 = 0.28209479177387814f;
__device__ __constant__ float C1 = 0.4886025119029199f;
__device__ __constant__ float C2_[5] = {1.0925484305920792f, -1.0925484305920792f,
                                        0.31539156525252005f, -1.0925484305920792f,
                                        0.5462742152960396f};
__device__ __constant__ float C3_[7] = {-0.5900435899266435f, 2.890611442640554f,
                                        -0.4570457994644658f, 0.3731763325901154f,
                                        -0.4570457994644658f, 1.445305721320277f,
                                        -0.5900435899266435f};

// Two-level monotonic barrier (replay-safe; counters only grow, +GRID3/launch).
// 512 blocks: 16 leaves × 32 arrivals; 32nd arrival of a leaf round bumps root.
__device__ __forceinline__ void gbar() {
    __syncthreads();
    __threadfence();
    if (threadIdx.x == 0) {
        int leaf = blockIdx.x & 15;
        unsigned int old = atomicAdd(&g_leaf[leaf], 1u);
        if ((old & 31u) == 31u) atomicAdd(&g_root, 1u);
        unsigned int target = ((old >> 5) + 1u) * 16u;
        while (*((volatile unsigned int*)&g_root) < target) { __nanosleep(32); }
        __threadfence();
    }
    __syncthreads();
}

__global__ void __launch_bounds__(BLK3, 4) fused_kernel(
        const float* __restrict__ pw,
        const float* __restrict__ lowsh,
        const float* __restrict__ highsh,
        const float* __restrict__ rawop,
        const float* __restrict__ sraw,
        const float* __restrict__ rraw,
        const float* __restrict__ Rcw,
        const float* __restrict__ tcw,
        float* __restrict__ out,
        int n) {
    int t   = threadIdx.x;
    int blk = blockIdx.x;
    int gid = blk * BLK3 + t;

    // ------------- Phase A: geom || color || rank on disjoint threads -------------
    if (gid < n) {
        // ---- geom ----
        int i = gid;

        float R00=Rcw[0],R01=Rcw[1],R02=Rcw[2];
        float R10=Rcw[3],R11=Rcw[4],R12=Rcw[5];
        float R20=Rcw[6],R21=Rcw[7],R22=Rcw[8];
        float t0=tcw[0], t1=tcw[1], t2=tcw[2];

        float px = pw[i*3+0], py = pw[i*3+1], pz = pw[i*3+2];

        float pc0 = R00*px + R01*py + R02*pz + t0;
        float pc1 = R10*px + R11*py + R12*pz + t1;
        float pc2 = fmaf(R22, pz, fmaf(R21, py, fmaf(R20, px, t2)));  // matches rank's z
        float invz = 1.0f / pc2;
        float u = FXc * pc0 * invz + 0.5f * IMG_W;
        float v = FYc * pc1 * invz + 0.5f * IMG_H;

        float op = 1.0f / (1.0f + __expf(-rawop[i]));

        float s0 = __expf(sraw[i*3+0]);
        float s1 = __expf(sraw[i*3+1]);
        float s2 = __expf(sraw[i*3+2]);

        float qw = rraw[i*4+0], qx = rraw[i*4+1], qy = rraw[i*4+2], qz = rraw[i*4+3];
        float qn = rsqrtf(qw*qw + qx*qx + qy*qy + qz*qz);
        qw *= qn; qx *= qn; qy *= qn; qz *= qn;

        float Rg00 = 1.0f - 2.0f*(qy*qy + qz*qz);
        float Rg01 = 2.0f*(qx*qy - qw*qz);
        float Rg02 = 2.0f*(qx*qz + qw*qy);
        float Rg10 = 2.0f*(qx*qy + qw*qz);
        float Rg11 = 1.0f - 2.0f*(qx*qx + qz*qz);
        float Rg12 = 2.0f*(qy*qz - qw*qx);
        float Rg20 = 2.0f*(qx*qz - qw*qy);
        float Rg21 = 2.0f*(qy*qz + qw*qx);
        float Rg22 = 1.0f - 2.0f*(qx*qx + qy*qy);

        float M00 = Rg00*s0, M01 = Rg01*s1, M02 = Rg02*s2;
        float M10 = Rg10*s0, M11 = Rg11*s1, M12 = Rg12*s2;
        float M20 = Rg20*s0, M21 = Rg21*s1, M22 = Rg22*s2;

        float j00 = FXc*invz, j02 = -FXc*pc0*invz*invz;
        float j11 = FYc*invz, j12 = -FYc*pc1*invz*invz;
        float T00 = j00*R00 + j02*R20;
        float T01 = j00*R01 + j02*R21;
        float T02 = j00*R02 + j02*R22;
        float T10 = j11*R10 + j12*R20;
        float T11 = j11*R11 + j12*R21;
        float T12 = j11*R12 + j12*R22;

        float V00 = T00*M00 + T01*M10 + T02*M20;
        float V01 = T00*M01 + T01*M11 + T02*M21;
        float V02 = T00*M02 + T01*M12 + T02*M22;
        float V10 = T10*M00 + T11*M10 + T12*M20;
        float V11 = T10*M01 + T11*M11 + T12*M21;
        float V12 = T10*M02 + T11*M12 + T12*M22;

        float a  = V00*V00 + V01*V01 + V02*V02 + 0.3f;
        float b  = V00*V10 + V01*V11 + V02*V12;
        float cc = V10*V10 + V11*V11 + V12*V12 + 0.3f;
        float det = a*cc - b*b;
        float idet = 1.0f / det;
        float ia =  cc * idet;
        float ib = -b  * idet;
        float ic =  a  * idet;

        float op_eff = (pc2 > 0.2f) ? op : 0.0f;

        float A2  = -0.5f * ia * LOG2E;
        float B2  = -ib * LOG2E;
        float Cc2 = -0.5f * ic * LOG2E;

        float mid  = 0.5f * (a + cc);
        float disc = sqrtf(0.25f * (a - cc) * (a - cc) + b * b);
        float lmax = mid + disc;
        float t255 = 255.0f * op_eff;
        float r2 = (t255 > 1.0f) ? 2.0f * __logf(t255) * lmax * 1.0002f : -1.0f;

        g_a[i] = make_float4(u, v, A2, B2);
        g_d[i] = make_float4(Cc2, op_eff, r2, 0.0f);
    } else if (gid < 4 * n) {
        // ---- color: SH -> rgb, 3 threads per gaussian (one channel each) ----
        int cid = gid - n;
        int i  = cid / 3;
        int ch = cid - 3 * i;

        float R00=Rcw[0],R01=Rcw[1],R02=Rcw[2];
        float R10=Rcw[3],R11=Rcw[4],R12=Rcw[5];
        float R20=Rcw[6],R21=Rcw[7],R22=Rcw[8];
        float t0=tcw[0], t1=tcw[1], t2=tcw[2];

        float px = pw[i*3+0], py = pw[i*3+1], pz = pw[i*3+2];

        float dx0 = px + (R00*t0 + R10*t1 + R20*t2);
        float dy0 = py + (R01*t0 + R11*t1 + R21*t2);
        float dz0 = pz + (R02*t0 + R12*t1 + R22*t2);
        float dn = rsqrtf(dx0*dx0 + dy0*dy0 + dz0*dz0);
        float x = dx0*dn, y = dy0*dn, z = dz0*dn;

        float xx = x*x, yy = y*y, zz = z*z;
        float xy = x*y, yz = y*z, xz = x*z;

        const float* hs = highsh + i*45 + ch;
        float res = C0 * lowsh[i*3+ch];
        res += (-C1*y) * hs[0*3] + (C1*z) * hs[1*3] + (-C1*x) * hs[2*3];
        res += (C2_[0]*xy) * hs[3*3] + (C2_[1]*yz) * hs[4*3]
             + (C2_[2]*(2.0f*zz - xx - yy)) * hs[5*3]
             + (C2_[3]*xz) * hs[6*3] + (C2_[4]*(xx - yy)) * hs[7*3];
        res += (C3_[0]*y*(3.0f*xx - yy)) * hs[8*3]
             + (C3_[1]*xy*z) * hs[9*3]
             + (C3_[2]*y*(4.0f*zz - xx - yy)) * hs[10*3]
             + (C3_[3]*z*(2.0f*zz - 3.0f*xx - 3.0f*yy)) * hs[11*3]
             + (C3_[4]*x*(4.0f*zz - xx - yy)) * hs[12*3]
             + (C3_[5]*z*(xx - yy)) * hs[13*3]
             + (C3_[6]*x*(xx - 3.0f*yy)) * hs[14*3];
        ((float*)&g_col[i])[ch] = fmaxf(res + 0.5f, 0.0f);
    } else {
        // ---- distributed stable rank, z computed on the fly (exact fmaf chain) ----
        int total = GRID3 * BLK3;
        int NS = total / n - 4;
        if (NS < 1) NS = 1;
        int rid = gid - 4 * n;
        if (rid < n * NS) {
            int i     = rid % n;
            int slice = rid / n;
            int JL = (n + NS - 1) / NS;
            int j0 = slice * JL;
            if (j0 < n) {
                int j1 = min(n, j0 + JL);
                float R20=Rcw[6], R21=Rcw[7], R22=Rcw[8], t2=tcw[2];
                float zi = fmaf(R22, pw[i*3+2], fmaf(R21, pw[i*3+1], fmaf(R20, pw[i*3+0], t2)));
                int r = 0;
                for (int j = j0; j < j1; j++) {
                    float zj = fmaf(R22, pw[j*3+2], fmaf(R21, pw[j*3+1], fmaf(R20, pw[j*3+0], t2)));
                    r += (zj < zi) || (zj == zi && j < i);
                }
                if (r) atomicAdd(&g_rank[i], r);
            }
        }
    }

    gbar();

    // ---------------- Phase B: scatter into depth order ----------------
    if (gid < n) {
        int r = g_rank[gid];
        float4 d = g_d[gid];
        float4 c = g_col[gid];
        s_a[r] = g_a[gid];
        s_b[r] = make_float4(d.x, d.y, c.x, c.y);
        s_c[r] = make_float2(c.z, d.z);   // (colB, r2)
    }

    gbar();

    // ------ Phase C: cull (order-preserving) + warp split-K blend + compose ------
    {
        __shared__ unsigned short slist[MAXN];
        __shared__ int wcnt[8];
        __shared__ float4 ca[8][32], cb[8][32];
        __shared__ float  ccb[8][32];
        __shared__ float4 part[8][32];

        // re-zero ranks for the NEXT launch (scatter above already consumed them)
        if (gid < n) g_rank[gid] = 0;

        int tlx = blk & (TILES_X - 1);
        int tly = blk >> 4;

        float xlo = tlx * TILE_W + 0.5f, xhi = tlx * TILE_W + (TILE_W - 0.5f);
        float ylo = tly * TILE_H + 0.5f, yhi = tly * TILE_H + (TILE_H - 0.5f);

        int wid = t >> 5, lid = t & 31;
        unsigned lmask = (1u << lid) - 1u;

        // order-preserving cull over the depth-sorted arrays
        int cnt = 0;
        for (int c = 0; c < n; c += BLK3) {
            int i = c + t;
            int pred = 0;
            if (i < n) {
                float4 A = s_a[i];
                float r2 = s_c[i].y;
                float cu = fminf(fmaxf(A.x, xlo), xhi);
                float cv = fminf(fmaxf(A.y, ylo), yhi);
                float ddx = A.x - cu, ddy = A.y - cv;
                pred = (ddx * ddx + ddy * ddy <= r2) ? 1 : 0;
            }
            unsigned m = __ballot_sync(0xffffffffu, pred);
            if (lid == 0) wcnt[wid] = __popc(m);
            __syncthreads();
            int off = cnt + __popc(m & lmask);
            int tot = 0;
            #pragma unroll
            for (int w = 0; w < 8; w++) {
                int c8 = wcnt[w];
                if (w < wid) off += c8;
                tot += c8;
            }
            if (pred) slist[off] = (unsigned short)i;
            __syncthreads();
            cnt += tot;
        }

        // warp split-K: warp q blends depth-segment q for its 32 pixels
        int q = wid;
        int p = lid;
        float pxf = tlx * TILE_W + (p & 7) + 0.5f;
        float pyf = tly * TILE_H + (p >> 3) + 0.5f;

        int L8 = (cnt + 7) >> 3;
        int qbeg = q * L8;
        int qend = min(cnt, qbeg + L8);

        float T = 1.0f, cr = 0.0f, cg = 0.0f, cbl = 0.0f;

        for (int base = 0; base < L8; base += 32) {
            if (__all_sync(0xffffffffu, T < 1e-5f)) break;
            int src = qbeg + base + p;
            if (src < qend) {
                int idx = slist[src];
                ca[q][p]  = s_a[idx];
                cb[q][p]  = s_b[idx];
                ccb[q][p] = s_c[idx].x;
            }
            __syncwarp();
            int m = min(32, qend - (qbeg + base));
            #pragma unroll 4
            for (int k = 0; k < m; k++) {
                float4 A = ca[q][k];
                float4 B = cb[q][k];
                float dx = A.x - pxf;
                float dy = A.y - pyf;
                float pp = A.z * dx * dx;
                pp = fmaf(B.x, dy * dy, pp);
                pp = fmaf(A.w, dx * dy, pp);
                pp = fminf(pp, 0.0f);
                float gw;
                asm("ex2.approx.f32 %0, %1;" : "=f"(gw) : "f"(pp));
                float alpha = fminf(0.99f, B.y * gw);
                alpha = (alpha >= (1.0f / 255.0f)) ? alpha : 0.0f;
                float w = T * alpha;
                cr  = fmaf(w, B.z, cr);
                cg  = fmaf(w, B.w, cg);
                cbl = fmaf(w, ccb[q][k], cbl);
                T = fmaf(-alpha, T, T);
            }
            __syncwarp();
        }

        part[q][p] = make_float4(cr, cg, cbl, T);
        __syncthreads();

        // compose 8 segments front-to-back (threads 0..31)
        if (t < 32) {
            float Tc = 1.0f, rr = 0.0f, gg = 0.0f, bb = 0.0f;
            #pragma unroll
            for (int s = 0; s < 8; s++) {
                float4 P = part[s][t];
                rr = fmaf(Tc, P.x, rr);
                gg = fmaf(Tc, P.y, gg);
                bb = fmaf(Tc, P.z, bb);
                Tc *= P.w;
            }
            int pxi = tlx * TILE_W + (t & 7);
            int pyi = tly * TILE_H + (t >> 3);
            int o = (pyi * IMG_W + pxi) * 3;
            out[o + 0] = rr;
            out[o + 1] = gg;
            out[o + 2] = bb;
        }
    }
}

extern "C" void kernel_launch(void* const* d_in, const int* in_sizes, int n_in,
                              void* d_out, int out_size) {
    const float* pw     = (const float*)d_in[0];
    const float* lowsh  = (const float*)d_in[1];
    const float* highsh = (const float*)d_in[2];
    const float* rawop  = (const float*)d_in[3];
    const float* sraw   = (const float*)d_in[4];
    const float* rraw   = (const float*)d_in[5];
    const float* Rcw    = (const float*)d_in[6];
    const float* tcw    = (const float*)d_in[7];
    int n = in_sizes[0] / 3;

    fused_kernel<<<GRID3, BLK3>>>(pw, lowsh, highsh, rawop, sraw, rraw, Rcw, tcw,
                                  (float*)d_out, n);
}